// round 1
// baseline (speedup 1.0000x reference)
#include <cuda_runtime.h>

#define P    8192
#define NB   4
#define NPTS 2048
#define Dd   3
#define Cc   64
#define HH   512
#define MT   16
#define TPB  256
#define GRID (P/MT)
#define EPSBN 1e-4f

// ---------------- scratch (static __device__, no allocations) ----------------
__device__ float g_Gc0[P*HH];
__device__ float g_Gc1[P*HH];
__device__ float g_Gc2[P*HH];
__device__ float g_Gc3[P*Dd];
__device__ float g_Bc0[P*HH];
__device__ float g_Bc1[P*HH];
__device__ float g_Bc2[P*HH];
__device__ float g_Bc3[P*Dd];
__device__ float g_xs[P*Dd];   // current state x
__device__ float g_xe[P*Dd];   // stage input
__device__ float g_ax[P*Dd];   // RK4 dx accumulator
__device__ float g_lp[P];      // logp
__device__ float g_al[P];      // RK4 dlogp accumulator

__device__ __forceinline__ float sigf(float z) { return 1.f/(1.f+__expf(-z)); }

// ------------- precompute: bn1, lp init, Gc/Bc = hyper nets applied to c -------------
__global__ void __launch_bounds__(TPB) pre_kernel(
    const float* __restrict__ x, const float* __restrict__ c,
    const float* __restrict__ m1, const float* __restrict__ v1,
    const float* __restrict__ lg1, const float* __restrict__ be1,
    const float* __restrict__ Wg0, const float* __restrict__ bg0, const float* __restrict__ Wb0,
    const float* __restrict__ Wg1, const float* __restrict__ bg1, const float* __restrict__ Wb1,
    const float* __restrict__ Wg2, const float* __restrict__ bg2, const float* __restrict__ Wb2,
    const float* __restrict__ Wg3, const float* __restrict__ bg3, const float* __restrict__ Wb3)
{
    __shared__ float cs[MT][Cc];
    int tid = threadIdx.x;
    int base = blockIdx.x * MT;
    for (int i = tid; i < MT*Cc; i += TPB) cs[i>>6][i&63] = c[base*Cc + i];
    if (tid < MT*Dd) {
        int m = tid/Dd, d = tid - m*Dd, p = base+m;
        float val = (x[p*Dd+d] - m1[d]) * __expf(lg1[d]) * rsqrtf(v1[d]+EPSBN) + be1[d];
        g_xs[p*Dd+d] = val; g_xe[p*Dd+d] = val;
    }
    if (tid >= 64 && tid < 64+MT) {
        int m = tid-64, p = base+m;
        float ld = 0.f;
        #pragma unroll
        for (int d = 0; d < Dd; ++d) ld += lg1[d] - 0.5f*logf(v1[d]+EPSBN);
        g_lp[p] = -ld;
    }
    __syncthreads();

    const float* WGs[3] = {Wg0, Wg1, Wg2};
    const float* BGs[3] = {bg0, bg1, bg2};
    const float* WBs[3] = {Wb0, Wb1, Wb2};
    float* GCs[3] = {g_Gc0, g_Gc1, g_Gc2};
    float* BCs[3] = {g_Bc0, g_Bc1, g_Bc2};
    #pragma unroll
    for (int l = 0; l < 3; ++l) {
        const float* Wg = WGs[l]; const float* Wb = WBs[l];
        #pragma unroll
        for (int s = 0; s < 2; ++s) {
            int j = tid + s*TPB;
            float ag[MT], ab[MT];
            #pragma unroll
            for (int m = 0; m < MT; ++m) { ag[m]=0.f; ab[m]=0.f; }
            const float* wgr = Wg + j*(Cc+1) + 1;
            const float* wbr = Wb + j*(Cc+1) + 1;
            for (int q = 0; q < Cc; ++q) {
                float a = wgr[q], b = wbr[q];
                #pragma unroll
                for (int m = 0; m < MT; ++m) { ag[m] += a*cs[m][q]; ab[m] += b*cs[m][q]; }
            }
            float bgj = BGs[l][j];
            float* Gc = GCs[l]; float* Bc = BCs[l];
            for (int m = 0; m < MT; ++m) {
                int p = base+m;
                Gc[p*HH+j] = ag[m]+bgj; Bc[p*HH+j] = ab[m];
            }
        }
    }
    if (tid < Dd) {
        int j = tid;
        float ag[MT], ab[MT];
        #pragma unroll
        for (int m = 0; m < MT; ++m) { ag[m]=0.f; ab[m]=0.f; }
        const float* wgr = Wg3 + j*(Cc+1) + 1;
        const float* wbr = Wb3 + j*(Cc+1) + 1;
        for (int q = 0; q < Cc; ++q) {
            float a = wgr[q], b = wbr[q];
            #pragma unroll
            for (int m = 0; m < MT; ++m) { ag[m] += a*cs[m][q]; ab[m] += b*cs[m][q]; }
        }
        for (int m = 0; m < MT; ++m) {
            int p = base+m;
            g_Gc3[p*Dd+j] = ag[m]+bg3[j]; g_Bc3[p*Dd+j] = ab[m];
        }
    }
}

// ------------- GEMM micro-kernel: out(16x512) = in(16x512) @ W^T, 2 cols/thread -------------
__device__ __forceinline__ void gemm2x16(const float* __restrict__ W,
                                         const float* __restrict__ in_s,
                                         float* acc, int tid)
{
    const float4* wp0 = reinterpret_cast<const float4*>(W) + (size_t)tid*(HH/4);
    const float4* wp1 = reinterpret_cast<const float4*>(W) + (size_t)(tid+TPB)*(HH/4);
    const float4* ip  = reinterpret_cast<const float4*>(in_s);
    #pragma unroll 2
    for (int k4 = 0; k4 < HH/4; ++k4) {
        float4 wa = wp0[k4];
        float4 wb = wp1[k4];
        #pragma unroll
        for (int m = 0; m < MT; ++m) {
            float4 iv = ip[m*(HH/4) + k4];
            acc[m]    += iv.x*wa.x + iv.y*wa.y + iv.z*wa.z + iv.w*wa.w;
            acc[MT+m] += iv.x*wb.x + iv.y*wb.y + iv.z*wb.z + iv.w*wb.w;
        }
    }
}

// ------------- one dynamics eval (primal + 3 JVPs) + fused RK4 stage update -------------
__global__ void __launch_bounds__(TPB) eval_kernel(
    const float* __restrict__ W0, const float* __restrict__ b0,
    const float* __restrict__ Wg0, const float* __restrict__ Wb0,
    const float* __restrict__ W1, const float* __restrict__ b1,
    const float* __restrict__ Wg1, const float* __restrict__ Wb1,
    const float* __restrict__ W2, const float* __restrict__ b2,
    const float* __restrict__ Wg2, const float* __restrict__ Wb2,
    const float* __restrict__ W3, const float* __restrict__ b3,
    const float* __restrict__ Wg3, const float* __restrict__ Wb3,
    const float* __restrict__ sqrtT, int stage, float tc)
{
    extern __shared__ float sm[];
    float* h1  = sm;
    float* h2  = sm + 1*MT*HH;
    float* h3  = sm + 2*MT*HH;
    float* ua  = sm + 3*MT*HH;
    float* ub  = sm + 4*MT*HH;
    float* xin  = sm + 5*MT*HH;     // MT*3
    float* sdx  = xin + MT*Dd;      // MT*3
    float* sdiv = sdx + MT*Dd;      // MT

    int tid = threadIdx.x;
    int base = blockIdx.x*MT;
    float sT = sqrtT[0];
    float dt = sT*sT*(1.f/3.f);
    float t  = tc*dt;

    if (tid < MT*Dd) xin[tid] = g_xe[base*Dd + tid];
    if (tid < MT) sdiv[tid] = 0.f;
    __syncthreads();

    // primal L0: 3 -> 512
    #pragma unroll
    for (int s = 0; s < 2; ++s) {
        int j = tid + s*TPB;
        float wa = W0[j*3], wb = W0[j*3+1], wc = W0[j*3+2];
        float bj = b0[j];
        float wgt = Wg0[j*65], wbt = Wb0[j*65];
        for (int m = 0; m < MT; ++m) {
            int p = base+m;
            float z = xin[m*3]*wa + xin[m*3+1]*wb + xin[m*3+2]*wc + bj;
            float g = sigf(t*wgt + g_Gc0[(size_t)p*HH+j]);
            float bbv = t*wbt + g_Bc0[(size_t)p*HH+j];
            h1[m*HH+j] = tanhf(z*g + bbv);
        }
    }
    __syncthreads();

    // primal L1: 512 -> 512
    {
        float acc[2*MT];
        #pragma unroll
        for (int i = 0; i < 2*MT; ++i) acc[i]=0.f;
        gemm2x16(W1, h1, acc, tid);
        #pragma unroll
        for (int s = 0; s < 2; ++s) {
            int j = tid + s*TPB;
            float bj = b1[j], wgt = Wg1[j*65], wbt = Wb1[j*65];
            for (int m = 0; m < MT; ++m) {
                int p = base+m;
                float z = acc[s*MT+m] + bj;
                float g = sigf(t*wgt + g_Gc1[(size_t)p*HH+j]);
                float bbv = t*wbt + g_Bc1[(size_t)p*HH+j];
                h2[m*HH+j] = tanhf(z*g + bbv);
            }
        }
    }
    __syncthreads();

    // primal L2: 512 -> 512
    {
        float acc[2*MT];
        #pragma unroll
        for (int i = 0; i < 2*MT; ++i) acc[i]=0.f;
        gemm2x16(W2, h2, acc, tid);
        #pragma unroll
        for (int s = 0; s < 2; ++s) {
            int j = tid + s*TPB;
            float bj = b2[j], wgt = Wg2[j*65], wbt = Wb2[j*65];
            for (int m = 0; m < MT; ++m) {
                int p = base+m;
                float z = acc[s*MT+m] + bj;
                float g = sigf(t*wgt + g_Gc2[(size_t)p*HH+j]);
                float bbv = t*wbt + g_Bc2[(size_t)p*HH+j];
                h3[m*HH+j] = tanhf(z*g + bbv);
            }
        }
    }
    __syncthreads();

    // primal out: dx = (h3 @ W3^T + b3)*g3 + bb3  (warp-per-2-points)
    {
        int warp = tid>>5, lane = tid&31;
        for (int q = 0; q < 6; ++q) {
            int m = warp*2 + q/3;
            int d = q - (q/3)*3;
            float ssum = 0.f;
            const float* hr = h3 + m*HH;
            const float* wr = W3 + d*HH;
            for (int k = lane; k < HH; k += 32) ssum += hr[k]*wr[k];
            #pragma unroll
            for (int off = 16; off > 0; off >>= 1) ssum += __shfl_xor_sync(0xffffffffu, ssum, off);
            if (lane == 0) {
                int p = base+m;
                float z = ssum + b3[d];
                float g = sigf(t*Wg3[d*65] + g_Gc3[p*3+d]);
                float bbv = t*Wb3[d*65] + g_Bc3[p*3+d];
                sdx[m*3+d] = z*g + bbv;
            }
        }
    }
    __syncthreads();

    // in-place transform h_i -> q_i = (1-h_i^2)*gate_i  (reused by all 3 tangent dirs)
    #pragma unroll
    for (int s = 0; s < 2; ++s) {
        int j = tid + s*TPB;
        float wg0 = Wg0[j*65], wg1 = Wg1[j*65], wg2 = Wg2[j*65];
        for (int m = 0; m < MT; ++m) {
            int p = base+m;
            float hv1 = h1[m*HH+j];
            h1[m*HH+j] = (1.f-hv1*hv1)*sigf(t*wg0 + g_Gc0[(size_t)p*HH+j]);
            float hv2 = h2[m*HH+j];
            h2[m*HH+j] = (1.f-hv2*hv2)*sigf(t*wg1 + g_Gc1[(size_t)p*HH+j]);
            float hv3 = h3[m*HH+j];
            h3[m*HH+j] = (1.f-hv3*hv3)*sigf(t*wg2 + g_Gc2[(size_t)p*HH+j]);
        }
    }
    __syncthreads();

    // tangent directions: div += g3[dir] * (q3 .* (W2 (q2 .* (W1 (q1 .* W0col))))) . W3row
    for (int dir = 0; dir < 3; ++dir) {
        #pragma unroll
        for (int s = 0; s < 2; ++s) {
            int j = tid + s*TPB;
            float w0k = W0[j*3+dir];
            for (int m = 0; m < MT; ++m) ua[m*HH+j] = h1[m*HH+j]*w0k;
        }
        __syncthreads();
        {
            float acc[2*MT];
            #pragma unroll
            for (int i = 0; i < 2*MT; ++i) acc[i]=0.f;
            gemm2x16(W1, ua, acc, tid);
            #pragma unroll
            for (int s = 0; s < 2; ++s) {
                int j = tid + s*TPB;
                for (int m = 0; m < MT; ++m) ub[m*HH+j] = h2[m*HH+j]*acc[s*MT+m];
            }
        }
        __syncthreads();
        {
            float acc[2*MT];
            #pragma unroll
            for (int i = 0; i < 2*MT; ++i) acc[i]=0.f;
            gemm2x16(W2, ub, acc, tid);
            #pragma unroll
            for (int s = 0; s < 2; ++s) {
                int j = tid + s*TPB;
                for (int m = 0; m < MT; ++m) ua[m*HH+j] = h3[m*HH+j]*acc[s*MT+m];
            }
        }
        __syncthreads();
        {
            int warp = tid>>5, lane = tid&31;
            const float* wr = W3 + dir*HH;
            for (int q = 0; q < 2; ++q) {
                int m = warp*2 + q;
                float ssum = 0.f;
                const float* urow = ua + m*HH;
                for (int k = lane; k < HH; k += 32) ssum += urow[k]*wr[k];
                #pragma unroll
                for (int off = 16; off > 0; off >>= 1) ssum += __shfl_xor_sync(0xffffffffu, ssum, off);
                if (lane == 0) {
                    int p = base+m;
                    float g = sigf(t*Wg3[dir*65] + g_Gc3[p*3+dir]);
                    sdiv[m] += ssum*g;
                }
            }
        }
        __syncthreads();
    }

    // fused RK4 stage update
    if (tid < MT) {
        int m = tid, p = base+m;
        float kl = -sdiv[m];
        float kx0 = sdx[m*3], kx1 = sdx[m*3+1], kx2 = sdx[m*3+2];
        if (stage == 0) {
            g_al[p] = kl;
            g_ax[p*3]=kx0; g_ax[p*3+1]=kx1; g_ax[p*3+2]=kx2;
            g_xe[p*3]  = g_xs[p*3]  + 0.5f*dt*kx0;
            g_xe[p*3+1]= g_xs[p*3+1]+ 0.5f*dt*kx1;
            g_xe[p*3+2]= g_xs[p*3+2]+ 0.5f*dt*kx2;
        } else if (stage == 1) {
            g_al[p] += 2.f*kl;
            g_ax[p*3]+=2.f*kx0; g_ax[p*3+1]+=2.f*kx1; g_ax[p*3+2]+=2.f*kx2;
            g_xe[p*3]  = g_xs[p*3]  + 0.5f*dt*kx0;
            g_xe[p*3+1]= g_xs[p*3+1]+ 0.5f*dt*kx1;
            g_xe[p*3+2]= g_xs[p*3+2]+ 0.5f*dt*kx2;
        } else if (stage == 2) {
            g_al[p] += 2.f*kl;
            g_ax[p*3]+=2.f*kx0; g_ax[p*3+1]+=2.f*kx1; g_ax[p*3+2]+=2.f*kx2;
            g_xe[p*3]  = g_xs[p*3]  + dt*kx0;
            g_xe[p*3+1]= g_xs[p*3+1]+ dt*kx1;
            g_xe[p*3+2]= g_xs[p*3+2]+ dt*kx2;
        } else {
            float c6 = dt*(1.f/6.f);
            g_lp[p] += c6*(g_al[p] + kl);
            float n0 = g_xs[p*3]   + c6*(g_ax[p*3]   + kx0);
            float n1 = g_xs[p*3+1] + c6*(g_ax[p*3+1] + kx1);
            float n2 = g_xs[p*3+2] + c6*(g_ax[p*3+2] + kx2);
            g_xs[p*3]=n0;   g_xe[p*3]=n0;
            g_xs[p*3+1]=n1; g_xe[p*3+1]=n1;
            g_xs[p*3+2]=n2; g_xe[p*3+2]=n2;
        }
    }
}

// ------------- bn2 + per-batch logp reduction + output -------------
__global__ void __launch_bounds__(TPB) final_kernel(
    const float* __restrict__ m2, const float* __restrict__ v2,
    const float* __restrict__ lg2, const float* __restrict__ be2,
    float* __restrict__ out)
{
    __shared__ float red[TPB];
    int b = blockIdx.x, tid = threadIdx.x;
    float sc[3], mn[3], bt[3];
    float ld2 = 0.f;
    #pragma unroll
    for (int d = 0; d < 3; ++d) {
        sc[d] = __expf(lg2[d]) * rsqrtf(v2[d]+EPSBN);
        mn[d] = m2[d]; bt[d] = be2[d];
        ld2 += lg2[d] - 0.5f*logf(v2[d]+EPSBN);
    }
    float part = 0.f;
    for (int n = tid; n < NPTS; n += TPB) {
        int p = b*NPTS + n;
        #pragma unroll
        for (int d = 0; d < 3; ++d)
            out[p*3+d] = (g_xs[p*3+d]-mn[d])*sc[d] + bt[d];
        part += g_lp[p] - ld2;
    }
    red[tid] = part;
    __syncthreads();
    for (int off = TPB/2; off > 0; off >>= 1) {
        if (tid < off) red[tid] += red[tid+off];
        __syncthreads();
    }
    if (tid == 0) out[P*3 + b] = red[0];
}

// ---------------- launch ----------------
extern "C" void kernel_launch(void* const* d_in, const int* in_sizes, int n_in,
                              void* d_out, int out_size)
{
    const float* x    = (const float*)d_in[0];
    const float* c    = (const float*)d_in[1];
    const float* bn1m = (const float*)d_in[2];
    const float* bn1v = (const float*)d_in[3];
    const float* bn1g = (const float*)d_in[4];
    const float* bn1b = (const float*)d_in[5];
    const float* bn2m = (const float*)d_in[6];
    const float* bn2v = (const float*)d_in[7];
    const float* bn2g = (const float*)d_in[8];
    const float* bn2b = (const float*)d_in[9];
    const float* sqT  = (const float*)d_in[10];
    const float *W[4], *bb[4], *Wg[4], *bg[4], *Wb[4];
    for (int i = 0; i < 4; ++i) {
        W[i]  = (const float*)d_in[11+5*i];
        bb[i] = (const float*)d_in[12+5*i];
        Wg[i] = (const float*)d_in[13+5*i];
        bg[i] = (const float*)d_in[14+5*i];
        Wb[i] = (const float*)d_in[15+5*i];
    }

    int smem = (5*MT*HH + MT*Dd*2 + MT) * (int)sizeof(float);
    cudaFuncSetAttribute(eval_kernel, cudaFuncAttributeMaxDynamicSharedMemorySize, smem);

    pre_kernel<<<GRID, TPB>>>(x, c, bn1m, bn1v, bn1g, bn1b,
                              Wg[0], bg[0], Wb[0], Wg[1], bg[1], Wb[1],
                              Wg[2], bg[2], Wb[2], Wg[3], bg[3], Wb[3]);

    const float tcs[4] = {0.f, 0.5f, 0.5f, 1.f};
    for (int i = 0; i < 3; ++i) {
        for (int s = 0; s < 4; ++s) {
            eval_kernel<<<GRID, TPB, smem>>>(
                W[0], bb[0], Wg[0], Wb[0],
                W[1], bb[1], Wg[1], Wb[1],
                W[2], bb[2], Wg[2], Wb[2],
                W[3], bb[3], Wg[3], Wb[3],
                sqT, s, (float)i + tcs[s]);
        }
    }

    final_kernel<<<NB, TPB>>>(bn2m, bn2v, bn2g, bn2b, (float*)d_out);
}